// round 17
// baseline (speedup 1.0000x reference)
#include <cuda_runtime.h>
#include <cstdint>

// Problem constants
#define B_  4
#define P_  64
#define S_  8
#define YD  16
#define GD  48
#define N_OUT      (B_ * P_ * P_ * S_ * S_)   // 1048576
#define TILE_OUT   256
#define TILE_BYTES (TILE_OUT * GD * 4)        // 49152 B per CTA tile
#define NCHUNK     (GD / 4)                   // 12 float4 chunks per row

__constant__ float c_wg[GD];

__device__ __forceinline__ uint32_t smem_u32(const void* p) {
    uint32_t a;
    asm("{ .reg .u64 t; cvta.to.shared.u64 t, %1; cvt.u32.u64 %0, t; }"
        : "=r"(a) : "l"(p));
    return a;
}

// Each CTA: bulk-copy its 48KB pg tile into smem (async proxy, bypasses the
// per-thread l1tex LDG miss machinery), compute 40 ky dots while the copy is
// in flight, then do 256 dot products out of smem against constant-memory Wg.
// The smem read schedule is rotated per-thread (jj = (tid + j) % 12) so every
// 8-thread LDS.128 phase hits all 32 banks conflict-free.
__global__ void __launch_bounds__(256) fused_bulk_kernel(
    const float* __restrict__ pg,
    const float* __restrict__ y,
    const float* __restrict__ Wy,
    const float* __restrict__ by,
    const float* __restrict__ bg,
    float* __restrict__ out)
{
    extern __shared__ float tile[];                 // TILE_BYTES dynamic
    __shared__ float ky1_sh[32];                    // [p2_local*8 + s2]
    __shared__ float ky2_sh[8];                     // [s1] (biases folded)
    __shared__ __align__(8) unsigned long long mbar;

    const int tid     = threadIdx.x;
    const int o_base  = blockIdx.x << 8;            // 256 outputs per CTA
    const int q_base  = o_base >> 6;                // o = q*64 + (s1*8+s2)
    const int p2_base = q_base & (P_ - 1);
    const int p1      = (q_base >> 6) & (P_ - 1);
    const int b       = q_base >> 12;

    const uint32_t mb = smem_u32(&mbar);

    // ---- init barrier (visible to all before anyone waits) ----
    if (tid == 0)
        asm volatile("mbarrier.init.shared.b64 [%0], 1;" :: "r"(mb));
    __syncthreads();

    // ---- launch the bulk copy (single thread) ----
    if (tid == 0) {
        asm volatile("mbarrier.arrive.expect_tx.shared.b64 _, [%0], %1;"
                     :: "r"(mb), "r"((uint32_t)TILE_BYTES));
        asm volatile(
            "cp.async.bulk.shared::cluster.global.mbarrier::complete_tx::bytes "
            "[%0], [%1], %2, [%3];"
            :: "r"(smem_u32(tile)),
               "l"(pg + (size_t)o_base * GD),
               "r"((uint32_t)TILE_BYTES),
               "r"(mb)
            : "memory");
    }

    // ---- ky prologue: overlaps the bulk copy ----
    if (tid < 40) {
        int row, woff;
        float a = 0.f;
        if (tid < 32) {                              // ky1 for (b, p2_base+p2l, s2)
            int p2l = tid >> 3, s2 = tid & 7;
            row  = (b * P_ + p2_base + p2l) * S_ + s2;
            woff = 0;
        } else {                                     // ky2 for (b, p1, s1) + by + bg
            int s1 = tid - 32;
            row  = (b * P_ + p1) * S_ + s1;
            woff = YD;
            a    = by[0] + bg[0];
        }
        const float4* y4 = reinterpret_cast<const float4*>(y + (size_t)row * YD);
        const float4* w4 = reinterpret_cast<const float4*>(Wy + woff);
#pragma unroll
        for (int j = 0; j < YD / 4; j++) {
            float4 yv = __ldg(y4 + j);
            float4 wv = __ldg(w4 + j);
            a += yv.x * wv.x + yv.y * wv.y + yv.z * wv.z + yv.w * wv.w;
        }
        if (tid < 32) ky1_sh[tid] = a;
        else          ky2_sh[tid - 32] = a;
    }
    __syncthreads();                                 // ky_sh visible to all

    // ---- wait for the bulk copy (acquire orders the smem reads below) ----
    {
        uint32_t done;
        asm volatile(
            "{\n\t"
            ".reg .pred p;\n\t"
            "mbarrier.try_wait.parity.acquire.cta.shared::cta.b64 p, [%1], 0;\n\t"
            "selp.b32 %0, 1, 0, p;\n\t"
            "}"
            : "=r"(done) : "r"(mb) : "memory");
        if (!done) {
            asm volatile(
                "{\n\t"
                ".reg .pred P1;\n\t"
                "WAIT_LOOP_%=:\n\t"
                "mbarrier.try_wait.parity.acquire.cta.shared::cta.b64 P1, [%0], 0, 0x989680;\n\t"
                "@P1 bra.uni WAIT_DONE_%=;\n\t"
                "bra.uni WAIT_LOOP_%=;\n\t"
                "WAIT_DONE_%=:\n\t"
                "}"
                :: "r"(mb) : "memory");
        }
    }

    // ---- 256 dot products out of smem, bank-conflict-free rotation ----
    const float4* t4 = reinterpret_cast<const float4*>(tile) + tid * NCHUNK;
    const int base = tid % NCHUNK;                  // rotation start
    float acc = 0.f;
#pragma unroll
    for (int j = 0; j < NCHUNK; j++) {
        int jj = base + j;
        if (jj >= NCHUNK) jj -= NCHUNK;
        float4 gv = t4[jj];
        acc += gv.x * c_wg[4 * jj + 0] + gv.y * c_wg[4 * jj + 1]
             + gv.z * c_wg[4 * jj + 2] + gv.w * c_wg[4 * jj + 3];
    }

    const int r = tid & 63;                          // r = s1*8 + s2
    out[o_base + tid] = acc + ky1_sh[(tid >> 6) * 8 + (r & 7)] + ky2_sh[r >> 3];
}

extern "C" void kernel_launch(void* const* d_in, const int* in_sizes, int n_in,
                              void* d_out, int out_size) {
    // metadata order: y, pairwise_g, Wy, by, Wg, bg
    const float* y  = (const float*)d_in[0];
    const float* pg = (const float*)d_in[1];
    const float* Wy = (const float*)d_in[2];
    const float* by = (const float*)d_in[3];
    const float* Wg = (const float*)d_in[4];
    const float* bg = (const float*)d_in[5];
    float* out = (float*)d_out;

    // Allow >48KB dynamic smem (idempotent; attribute, not an allocation).
    cudaFuncSetAttribute(fused_bulk_kernel,
                         cudaFuncAttributeMaxDynamicSharedMemorySize,
                         TILE_BYTES);

    cudaMemcpyToSymbolAsync(c_wg, Wg, GD * sizeof(float), 0,
                            cudaMemcpyDeviceToDevice, 0);

    fused_bulk_kernel<<<N_OUT / TILE_OUT, 256, TILE_BYTES>>>(
        pg, y, Wy, by, bg, out);
}